// round 1
// baseline (speedup 1.0000x reference)
#include <cuda_runtime.h>
#include <cstdint>

// Problem constants (fixed shapes from reference setup_inputs)
#define BB 2
#define NN 16384
#define MM 8192

// Pair-kernel tiling
#define THREADS 256
#define RR 8                    // n-points per thread
#define TN (RR * THREADS)       // 2048 n per block
#define NT (NN / TN)            // 8 n-tiles
#define MT 18                   // m-tiles
#define TM 456                  // 18*456 = 8208 >= 8192 (last tile padded)
#define NWARPS (THREADS / 32)

#define NEG_BIG -3.0e38f

// ---------------- scratch (device globals; no allocation allowed) ------------
__device__ float4 g_p2[BB * MM];        // (x, y, z, -0.5*|p|^2)
__device__ int    g_max1k[BB * NN];     // encoded max over m of c' (per n)
__device__ int    g_max2k[BB * MM];     // encoded max over n of (c' - h1) (per m)
__device__ int    g_wmaxk[BB];          // encoded max of weights per batch
__device__ float  g_part[16][3];        // deterministic partial sums (s0, s1, s2)

// Order-preserving float<->int encoding (monotone under signed int compare).
__device__ __forceinline__ int encf(float f) {
    int i = __float_as_int(f);
    return (i >= 0) ? i : (i ^ 0x7FFFFFFF);
}
__device__ __forceinline__ float decf(int k) {
    return __int_as_float((k >= 0) ? k : (k ^ 0x7FFFFFFF));
}

// ---------------- kernel 1: init scratch + precompute p2 float4 --------------
__global__ void k_prep(const float* __restrict__ p2) {
    int i = blockIdx.x * blockDim.x + threadIdx.x;   // grid covers BB*NN = 32768
    if (i < BB * NN) g_max1k[i] = (int)0x80000000;
    if (i < BB * MM) {
        g_max2k[i] = (int)0x80000000;
        float x = p2[i * 3 + 0];
        float y = p2[i * 3 + 1];
        float z = p2[i * 3 + 2];
        g_p2[i] = make_float4(x, y, z, -0.5f * (x * x + y * y + z * z));
    }
    if (i < BB) g_wmaxk[i] = (int)0x80000000;
}

// ---------------- kernel 2: pairwise distance / dual-min ---------------------
__global__ void __launch_bounds__(THREADS, 2) k_pairs(const float* __restrict__ p1) {
    const int b  = blockIdx.z;
    const int nb = blockIdx.y * TN;
    const int mb = blockIdx.x * TM;
    const int tid  = threadIdx.x;
    const int wid  = tid >> 5;
    const int lane = tid & 31;

    __shared__ float4 sm[TM];               // m-tile (x,y,z,-h2)
    __shared__ float  swm[NWARPS][TM];      // per-warp max over its n of (c' - h1)

    // stage m tile (sentinel pad: never wins any max)
    for (int j = tid; j < TM; j += THREADS) {
        int mg = mb + j;
        sm[j] = (mg < MM) ? g_p2[b * MM + mg] : make_float4(0.f, 0.f, 0.f, NEG_BIG);
    }

    // per-thread n registers
    float x[RR], y[RR], z[RR], h[RR], mx[RR];
#pragma unroll
    for (int i = 0; i < RR; i++) {
        int n = nb + i * THREADS + tid;     // NT*TN == NN exactly, always valid
        const float* p = p1 + ((size_t)b * NN + n) * 3;
        x[i] = p[0]; y[i] = p[1]; z[i] = p[2];
        h[i] = 0.5f * (x[i] * x[i] + y[i] * y[i] + z[i] * z[i]);
        mx[i] = NEG_BIG;
    }
    __syncthreads();

#pragma unroll 2
    for (int j = 0; j < TM; j++) {
        float4 mm = sm[j];                  // broadcast read
        float wv[RR];
#pragma unroll
        for (int i = 0; i < RR; i++) {
            float c = fmaf(x[i], mm.x, mm.w);   // acc init = -h2m
            c = fmaf(y[i], mm.y, c);
            c = fmaf(z[i], mm.z, c);
            mx[i] = fmaxf(mx[i], c);            // for min_dist1[n]
            wv[i] = c - h[i];                   // for min_dist2[m]
        }
        // in-thread tree max over RR
#pragma unroll
        for (int s = RR / 2; s > 0; s >>= 1)
#pragma unroll
            for (int i = 0; i < s; i++) wv[i] = fmaxf(wv[i], wv[i + s]);
        // warp butterfly max
        float t = wv[0];
#pragma unroll
        for (int off = 16; off > 0; off >>= 1)
            t = fmaxf(t, __shfl_xor_sync(0xffffffffu, t, off));
        if (lane == 0) swm[wid][j] = t;     // one writer per (warp, j): no race
    }

    // flush min_dist1 partials: max over this block's m-tile, merged globally
#pragma unroll
    for (int i = 0; i < RR; i++) {
        int n = nb + i * THREADS + tid;
        atomicMax(&g_max1k[b * NN + n], encf(mx[i]));
    }
    __syncthreads();

    // flush min_dist2 partials: reduce warp rows, merge globally
    for (int j = tid; j < TM; j += THREADS) {
        int mg = mb + j;
        if (mg < MM) {
            float v = swm[0][j];
#pragma unroll
            for (int w = 1; w < NWARPS; w++) v = fmaxf(v, swm[w][j]);
            atomicMax(&g_max2k[b * MM + mg], encf(v));
        }
    }
}

// ---------------- kernel 3: softmax max per batch ----------------------------
__global__ void k_wmax(const float* __restrict__ w) {
    int b = blockIdx.x >> 3;
    int chunk = blockIdx.x & 7;              // 8 chunks of 2048 per batch
    int base = b * NN + chunk * 2048;
    float lm = NEG_BIG;
    for (int i = threadIdx.x; i < 2048; i += 256) lm = fmaxf(lm, w[base + i]);
    __shared__ float s[256];
    s[threadIdx.x] = lm;
    __syncthreads();
    for (int st = 128; st > 0; st >>= 1) {
        if (threadIdx.x < st) s[threadIdx.x] = fmaxf(s[threadIdx.x], s[threadIdx.x + st]);
        __syncthreads();
    }
    if (threadIdx.x == 0) atomicMax(&g_wmaxk[b], encf(s[0]));
}

// ---------------- kernel 4: deterministic partial sums -----------------------
__global__ void k_partial(const float* __restrict__ p1, const float* __restrict__ w) {
    int b = blockIdx.x >> 3;
    int chunk = blockIdx.x & 7;
    float wm = decf(g_wmaxk[b]);
    float s0 = 0.f, s1 = 0.f, s2 = 0.f;

    int nbase = chunk * 2048;
    for (int i = threadIdx.x; i < 2048; i += 256) {
        int n = nbase + i;
        float e = expf(w[b * NN + n] - wm);
        const float* p = p1 + ((size_t)b * NN + n) * 3;
        float xx = p[0], yy = p[1], zz = p[2];
        float h1 = 0.5f * (xx * xx + yy * yy + zz * zz);
        float md1 = 2.0f * (h1 - decf(g_max1k[b * NN + n]));
        s0 += e;
        s1 += e * md1;
    }
    int mbase = chunk * 1024;
    for (int i = threadIdx.x; i < 1024; i += 256)
        s2 += decf(g_max2k[b * MM + mbase + i]);

    __shared__ float sa[256], sb[256], sc[256];
    sa[threadIdx.x] = s0; sb[threadIdx.x] = s1; sc[threadIdx.x] = s2;
    __syncthreads();
    for (int st = 128; st > 0; st >>= 1) {
        if (threadIdx.x < st) {
            sa[threadIdx.x] += sa[threadIdx.x + st];
            sb[threadIdx.x] += sb[threadIdx.x + st];
            sc[threadIdx.x] += sc[threadIdx.x + st];
        }
        __syncthreads();
    }
    if (threadIdx.x == 0) {
        g_part[blockIdx.x][0] = sa[0];
        g_part[blockIdx.x][1] = sb[0];
        g_part[blockIdx.x][2] = sc[0];
    }
}

// ---------------- kernel 5: final combine (fixed order => deterministic) -----
__global__ void k_final(float* __restrict__ out) {
    if (threadIdx.x == 0 && blockIdx.x == 0) {
        float loss = 0.f;
        for (int b = 0; b < BB; b++) {
            float s0 = 0.f, s1 = 0.f, s2 = 0.f;
            for (int k = 0; k < 8; k++) {
                s0 += g_part[b * 8 + k][0];
                s1 += g_part[b * 8 + k][1];
                s2 += g_part[b * 8 + k][2];
            }
            // loss_term1 = sum(softmax * min_dist1); loss_term2 = mean(min_dist2)
            loss += s1 / s0 + (-2.0f * s2 / (float)MM);
        }
        out[0] = loss / (float)BB;
    }
}

// ---------------- launch -----------------------------------------------------
extern "C" void kernel_launch(void* const* d_in, const int* in_sizes, int n_in,
                              void* d_out, int out_size) {
    const float* points1 = (const float*)d_in[0];   // (2,16384,3)
    const float* points2 = (const float*)d_in[1];   // (2,8192,3)
    const float* weights = (const float*)d_in[2];   // (2,16384)
    float* out = (float*)d_out;

    k_prep<<<(BB * NN + 255) / 256, 256>>>(points2);
    k_pairs<<<dim3(MT, NT, BB), THREADS>>>(points1);
    k_wmax<<<BB * 8, 256>>>(weights);
    k_partial<<<BB * 8, 256>>>(points1, weights);
    k_final<<<1, 32>>>(out);
}

// round 3
// speedup vs baseline: 1.3301x; 1.3301x over previous
#include <cuda_runtime.h>
#include <cstdint>

typedef unsigned long long ull;

// Problem constants (fixed shapes)
#define BB 2
#define NN 16384
#define MM 8192

// Pair-kernel tiling
#define THREADS 256
#define RP 8                      // packed n-pairs per thread
#define RR (2 * RP)               // 16 n per thread
#define TN (RR * THREADS)         // 4096 n per block
#define NT (NN / TN)              // 4 n-tiles
#define MT 37                     // m-tiles
#define TM 224                    // 37*224 = 8288 >= 8192
#define NWARPS (THREADS / 32)

#define NEG_BIG -3.0e38f

// ---------------- scratch (device globals) -----------------------------------
__device__ ull    g_p2d[BB * MM * 4];   // per m: {x,x},{y,y},{z,z},{-h2,-h2} packed b64
__device__ int    g_max1k[BB * NN];     // encoded max over m of c'  (per n)
__device__ int    g_max2k[BB * MM];     // encoded max over n of (c' - h1) (per m)
__device__ float  g_wblk[128];          // per-prep-block weight maxima
__device__ float  g_part[128][3];       // deterministic partial sums
__device__ unsigned int g_done;         // completion counter for last-block combine

// Order-preserving float<->int encoding (monotone under signed int compare).
__device__ __forceinline__ int encf(float f) {
    int i = __float_as_int(f);
    return (i >= 0) ? i : (i ^ 0x7FFFFFFF);
}
__device__ __forceinline__ float decf(int k) {
    return __int_as_float((k >= 0) ? k : (k ^ 0x7FFFFFFF));
}

// ---------------- packed f32x2 helpers (sm_100a) ------------------------------
__device__ __forceinline__ ull pk2(float lo, float hi) {
    ull r; asm("mov.b64 %0, {%1, %2};" : "=l"(r) : "f"(lo), "f"(hi)); return r;
}
__device__ __forceinline__ void upk2(ull v, float& lo, float& hi) {
    asm("mov.b64 {%0, %1}, %2;" : "=f"(lo), "=f"(hi) : "l"(v));
}
__device__ __forceinline__ ull ffma2(ull a, ull b, ull c) {
    ull d; asm("fma.rn.f32x2 %0, %1, %2, %3;" : "=l"(d) : "l"(a), "l"(b), "l"(c)); return d;
}
__device__ __forceinline__ ull fadd2(ull a, ull b) {
    ull d; asm("add.rn.f32x2 %0, %1, %2;" : "=l"(d) : "l"(a), "l"(b)); return d;
}

// ---------------- kernel 1: init + precompute packed p2 + weight block maxima -
__global__ void k_prep(const float* __restrict__ p2, const float* __restrict__ w) {
    int i = blockIdx.x * blockDim.x + threadIdx.x;   // 128*256 = 32768 = BB*NN
    if (i < BB * NN) g_max1k[i] = (int)0x80000000;
    if (i < BB * MM) {
        g_max2k[i] = (int)0x80000000;
        float x = p2[i * 3 + 0];
        float y = p2[i * 3 + 1];
        float z = p2[i * 3 + 2];
        float w2 = -0.5f * (x * x + y * y + z * z);
        g_p2d[i * 4 + 0] = pk2(x, x);
        g_p2d[i * 4 + 1] = pk2(y, y);
        g_p2d[i * 4 + 2] = pk2(z, z);
        g_p2d[i * 4 + 3] = pk2(w2, w2);
    }
    if (i == 0) g_done = 0;

    // per-block weight max (no atomics; reduced later in k_partial)
    __shared__ float s[THREADS];
    s[threadIdx.x] = w[i];
    __syncthreads();
    for (int st = THREADS / 2; st > 0; st >>= 1) {
        if (threadIdx.x < st) s[threadIdx.x] = fmaxf(s[threadIdx.x], s[threadIdx.x + st]);
        __syncthreads();
    }
    if (threadIdx.x == 0) g_wblk[blockIdx.x] = s[0];
}

// ---------------- kernel 2: pairwise dual-min (packed f32x2) ------------------
__global__ void __launch_bounds__(THREADS, 2) k_pairs(const float* __restrict__ p1) {
    const int b  = blockIdx.z;
    const int nb = blockIdx.y * TN;
    const int mb = blockIdx.x * TM;
    const int tid  = threadIdx.x;
    const int wid  = tid >> 5;
    const int lane = tid & 31;

    __shared__ ull smx[TM], smy[TM], smz[TM], smw[TM];   // pre-duplicated packed m-tile
    __shared__ float swm[NWARPS][TM];

    for (int j = tid; j < TM; j += THREADS) {
        int mg = mb + j;
        if (mg < MM) {
            const ull* g = g_p2d + (size_t)(b * MM + mg) * 4;
            smx[j] = g[0]; smy[j] = g[1]; smz[j] = g[2]; smw[j] = g[3];
        } else {
            smx[j] = 0; smy[j] = 0; smz[j] = 0;
            smw[j] = pk2(NEG_BIG, NEG_BIG);              // sentinel: never wins
        }
    }

    // per-thread n registers (packed pairs of consecutive n)
    ull x2[RP], y2[RP], z2[RP], hn2[RP];
    float mx[RR];
#pragma unroll
    for (int p = 0; p < RP; p++) {
        int n0 = nb + (p * THREADS + tid) * 2;           // always < NN (exact tiling)
        const float2* q = (const float2*)(p1 + ((size_t)b * NN + n0) * 3);
        float2 a = q[0], bb2 = q[1], cc = q[2];
        float X0 = a.x,  Y0 = a.y,  Z0 = bb2.x;
        float X1 = bb2.y, Y1 = cc.x, Z1 = cc.y;
        x2[p] = pk2(X0, X1);
        y2[p] = pk2(Y0, Y1);
        z2[p] = pk2(Z0, Z1);
        float h0 = 0.5f * (X0 * X0 + Y0 * Y0 + Z0 * Z0);
        float h1 = 0.5f * (X1 * X1 + Y1 * Y1 + Z1 * Z1);
        hn2[p] = pk2(-h0, -h1);
        mx[2 * p] = NEG_BIG; mx[2 * p + 1] = NEG_BIG;
    }
    __syncthreads();

#pragma unroll 2
    for (int j = 0; j < TM; j++) {
        ull bx = smx[j], by = smy[j], bz = smz[j], bw = smw[j];  // LDS.64 broadcasts
        float wm0 = NEG_BIG, wm1 = NEG_BIG;
#pragma unroll
        for (int p = 0; p < RP; p++) {
            ull c2 = ffma2(x2[p], bx, bw);               // acc init = -h2m
            c2 = ffma2(y2[p], by, c2);
            c2 = ffma2(z2[p], bz, c2);
            ull w2 = fadd2(c2, hn2[p]);                  // c' - h1
            float cl, ch; upk2(c2, cl, ch);              // reg-pair alias (free)
            mx[2 * p]     = fmaxf(mx[2 * p], cl);
            mx[2 * p + 1] = fmaxf(mx[2 * p + 1], ch);
            float wl, wh; upk2(w2, wl, wh);
            wm0 = fmaxf(wm0, wl);
            wm1 = fmaxf(wm1, wh);
        }
        float t = fmaxf(wm0, wm1);
#pragma unroll
        for (int off = 16; off > 0; off >>= 1)
            t = fmaxf(t, __shfl_xor_sync(0xffffffffu, t, off));
        if (lane == 0) swm[wid][j] = t;
    }

    // flush side 1: per-n max over this m-tile → global encoded atomicMax
#pragma unroll
    for (int p = 0; p < RP; p++) {
        int n0 = nb + (p * THREADS + tid) * 2;
        atomicMax(&g_max1k[b * NN + n0],     encf(mx[2 * p]));
        atomicMax(&g_max1k[b * NN + n0 + 1], encf(mx[2 * p + 1]));
    }
    __syncthreads();

    // flush side 2: reduce warp rows, merge globally
    for (int j = tid; j < TM; j += THREADS) {
        int mg = mb + j;
        if (mg < MM) {
            float v = swm[0][j];
#pragma unroll
            for (int w = 1; w < NWARPS; w++) v = fmaxf(v, swm[w][j]);
            atomicMax(&g_max2k[b * MM + mg], encf(v));
        }
    }
}

// ---------------- kernel 3: partial sums + fused deterministic final ----------
__global__ void k_partial(const float* __restrict__ p1, const float* __restrict__ w,
                          float* __restrict__ out) {
    const int blk = blockIdx.x;               // 128 blocks
    const int b = blk >> 6;
    const int idx = blk & 63;
    const int tid = threadIdx.x;

    __shared__ float sa[THREADS], sb[THREADS], sc[THREADS];

    // batch weight max from per-block partials (deterministic tree)
    sa[tid] = (tid < 64) ? g_wblk[b * 64 + tid] : NEG_BIG;
    __syncthreads();
    for (int st = 128; st > 0; st >>= 1) {
        if (tid < st) sa[tid] = fmaxf(sa[tid], sa[tid + st]);
        __syncthreads();
    }
    float wm = sa[0];
    __syncthreads();

    // n side: 256 n per block
    int n = idx * 256 + tid;
    int gn = b * NN + n;
    float e = expf(w[gn] - wm);
    const float* p = p1 + (size_t)gn * 3;
    float xx = p[0], yy = p[1], zz = p[2];
    float h1 = 0.5f * (xx * xx + yy * yy + zz * zz);
    float md1 = 2.0f * (h1 - decf(g_max1k[gn]));
    float s0 = e;
    float s1 = e * md1;

    // m side: 128 m per block
    float s2 = 0.f;
    if (tid < 128) s2 = decf(g_max2k[b * MM + idx * 128 + tid]);

    sa[tid] = s0; sb[tid] = s1; sc[tid] = s2;
    __syncthreads();
    for (int st = 128; st > 0; st >>= 1) {
        if (tid < st) {
            sa[tid] += sa[tid + st];
            sb[tid] += sb[tid + st];
            sc[tid] += sc[tid + st];
        }
        __syncthreads();
    }

    __shared__ int last;
    if (tid == 0) {
        g_part[blk][0] = sa[0];
        g_part[blk][1] = sb[0];
        g_part[blk][2] = sc[0];
        __threadfence();
        unsigned int prev = atomicAdd(&g_done, 1u);
        last = (prev == 127u) ? 1 : 0;
    }
    __syncthreads();
    if (!last) return;
    __threadfence();

    // last block: deterministic fixed-order combine of 128 partials
    float t0 = 0.f, t1 = 0.f, t2 = 0.f;
    if (tid < 128) {
        volatile float* gp = &g_part[tid][0];
        t0 = gp[0]; t1 = gp[1]; t2 = gp[2];
    }
    sa[tid] = t0; sb[tid] = t1; sc[tid] = t2;
    __syncthreads();
    // reduce within each batch half [0,64) and [64,128)
    for (int st = 32; st > 0; st >>= 1) {
        if (tid < 128 && (tid & 63) < st) {
            sa[tid] += sa[tid + st];
            sb[tid] += sb[tid + st];
            sc[tid] += sc[tid + st];
        }
        __syncthreads();
    }
    if (tid == 0) {
        float loss = 0.f;
        loss += sb[0]  / sa[0]  + (-2.0f * sc[0]  / (float)MM);
        loss += sb[64] / sa[64] + (-2.0f * sc[64] / (float)MM);
        out[0] = loss / (float)BB;
    }
}

// ---------------- launch -----------------------------------------------------
extern "C" void kernel_launch(void* const* d_in, const int* in_sizes, int n_in,
                              void* d_out, int out_size) {
    const float* points1 = (const float*)d_in[0];   // (2,16384,3)
    const float* points2 = (const float*)d_in[1];   // (2,8192,3)
    const float* weights = (const float*)d_in[2];   // (2,16384)
    float* out = (float*)d_out;

    k_prep<<<128, THREADS>>>(points2, weights);
    k_pairs<<<dim3(MT, NT, BB), THREADS>>>(points1);
    k_partial<<<128, THREADS>>>(points1, weights, out);
}